// round 1
// baseline (speedup 1.0000x reference)
#include <cuda_runtime.h>
#include <math.h>

#define NVOX 32
#define VX 32768           // 32^3
#define BB 2
#define NPTS 100000

// ---------------- scratch (device globals; no allocation allowed) ----------
__device__ float g_grid[BB * 256 * VX];        // voxel feature grid (B,256,32^3)  67MB
__device__ float g_l2[BB * 1024 * 512];        // conv2 output (B,1024,8^3)        4MB
__device__ float g_w2t[128 * 256];             // W2 transposed [k][co]
__device__ float g_wc1t[256 * 27 * 512];       // Wc1 -> [ci][tap][co]             14MB
__device__ float g_wc2t[512 * 27 * 1024];      // Wc2 -> [ci][tap][co]             57MB
__device__ float g_wtt[8 * 1024 * 512];        // Wt  -> [tap][ci][co]             17MB

// ---------------- zero the grid ------------------------------------------
__global__ void k_zero(float* __restrict__ p, int n4) {
    float4 z = make_float4(0.f, 0.f, 0.f, 0.f);
    for (int i = blockIdx.x * blockDim.x + threadIdx.x; i < n4;
         i += gridDim.x * blockDim.x)
        reinterpret_cast<float4*>(p)[i] = z;
}

// ---------------- weight transforms --------------------------------------
__global__ void k_w2t(const float* __restrict__ w2) {
    int i = blockIdx.x * blockDim.x + threadIdx.x;   // 32768 total
    if (i < 128 * 256) {
        int k = i >> 8, co = i & 255;
        g_w2t[i] = w2[co * 128 + k];
    }
}

// w[co][ci][27] -> out[(ci*27+tap)*CO + co]
__global__ void k_wconv_t(const float* __restrict__ w, float* __restrict__ out,
                          int CI, int CO) {
    long long total = (long long)CI * CO * 27;
    for (long long i = blockIdx.x * (long long)blockDim.x + threadIdx.x; i < total;
         i += (long long)gridDim.x * blockDim.x) {
        int co = (int)(i % CO);
        long long r = i / CO;
        int tap = (int)(r % 27);
        int ci = (int)(r / 27);
        out[i] = w[((long long)co * CI + ci) * 27 + tap];
    }
}

// Wt[ci(1024)][co(512)][8] -> g_wtt[(tap*1024+ci)*512 + co]
__global__ void k_wtt(const float* __restrict__ w) {
    int total = 8 * 1024 * 512;
    for (int i = blockIdx.x * blockDim.x + threadIdx.x; i < total;
         i += gridDim.x * blockDim.x) {
        int co = i & 511;
        int ci = (i >> 9) & 1023;
        int tap = i >> 19;
        g_wtt[i] = w[(((long long)ci << 9) + co) * 8 + tap];
    }
}

// ---------------- point MLP + segment-max scatter -------------------------
// 64 points per block. H = relu(W1 xc + b1) in smem; F = relu(W2 H + b2) via
// register-blocked 256x64x128 GEMM (8co x 8pt per thread); atomicMax into grid.
__global__ void __launch_bounds__(256) k_mlp(const float* __restrict__ pc,
                                             const float* __restrict__ W1,
                                             const float* __restrict__ b1,
                                             const float* __restrict__ b2) {
    __shared__ float xcs[64][4];
    __shared__ int pb[64];
    __shared__ float Hs[128][64];
    const int tid = threadIdx.x;
    const int g0 = blockIdx.x * 64;

    if (tid < 64) {
        int g = g0 + tid;
        int b = g / NPTS;
        float x = pc[g * 3 + 0], y = pc[g * 3 + 1], z = pc[g * 3 + 2];
        int ix = (int)floorf((x + 1.f) * 16.f);
        int iy = (int)floorf((y + 1.f) * 16.f);
        int iz = (int)floorf((z + 1.f) * 16.f);
        xcs[tid][0] = x - (ix * 0.0625f + 0.03125f - 1.f);
        xcs[tid][1] = y - (iy * 0.0625f + 0.03125f - 1.f);
        xcs[tid][2] = z - (iz * 0.0625f + 0.03125f - 1.f);
        pb[tid] = b * (256 * VX) + ix * 1024 + iy * 32 + iz;
    }
    __syncthreads();

    // H: 128x64 values, 32 per thread
#pragma unroll
    for (int i = 0; i < 32; i++) {
        int lin = i * 256 + tid;
        int k = lin >> 6, p = lin & 63;
        float a = b1[k] + W1[k * 3 + 0] * xcs[p][0] + W1[k * 3 + 1] * xcs[p][1] +
                  W1[k * 3 + 2] * xcs[p][2];
        Hs[k][p] = fmaxf(a, 0.f);
    }
    __syncthreads();

    const int cg = tid & 31, pg = tid >> 5;
    const int co0 = cg * 8, p0 = pg * 8;
    float acc[8][8];
    {
        float4 bA = *reinterpret_cast<const float4*>(&b2[co0]);
        float4 bB = *reinterpret_cast<const float4*>(&b2[co0 + 4]);
        float bi[8] = {bA.x, bA.y, bA.z, bA.w, bB.x, bB.y, bB.z, bB.w};
#pragma unroll
        for (int c = 0; c < 8; c++)
#pragma unroll
            for (int p = 0; p < 8; p++) acc[c][p] = bi[c];
    }
#pragma unroll 4
    for (int k = 0; k < 128; k++) {
        float4 wA = *reinterpret_cast<const float4*>(&g_w2t[k * 256 + co0]);
        float4 wB = *reinterpret_cast<const float4*>(&g_w2t[k * 256 + co0 + 4]);
        float4 hA = *reinterpret_cast<const float4*>(&Hs[k][p0]);
        float4 hB = *reinterpret_cast<const float4*>(&Hs[k][p0 + 4]);
        float wv[8] = {wA.x, wA.y, wA.z, wA.w, wB.x, wB.y, wB.z, wB.w};
        float hv[8] = {hA.x, hA.y, hA.z, hA.w, hB.x, hB.y, hB.z, hB.w};
#pragma unroll
        for (int c = 0; c < 8; c++)
#pragma unroll
            for (int p = 0; p < 8; p++) acc[c][p] += wv[c] * hv[p];
    }
    // scatter: atomicMax (values >= 0, grid zero-initialized)
#pragma unroll
    for (int c = 0; c < 8; c++) {
        int cob = (co0 + c) * VX;
#pragma unroll
        for (int p = 0; p < 8; p++) {
            float v = acc[c][p];
            if (v > 0.f)
                atomicMax(reinterpret_cast<int*>(&g_grid[pb[p0 + p] + cob]),
                          __float_as_int(v));
        }
    }
}

// ---------------- direct conv3d (k=3, pad=1) + relu + maxpool2 ------------
// block: 32 c_out x 4x4x4 spatial (pre-pool). 128 threads: tx=spatial row
// (dz,dy), ty=co quad. c_in chunks of 8 staged in smem. FFMA-bound inner loop.
template <int CI, int CO, int S>
__global__ void __launch_bounds__(128) k_conv(const float* __restrict__ in,
                                              long long in_bstr, int in_cstr,
                                              const float* __restrict__ wt,
                                              const float* __restrict__ bias,
                                              float* __restrict__ out,
                                              long long out_bstr, int out_cstr) {
    constexpr int NT = S / 4;
    __shared__ float in_s[8 * 224];
    __shared__ float w_s[8 * 27 * 32];
    __shared__ float pool_s[32 * 64];

    const int tid = threadIdx.x;
    const int bid = blockIdx.x;
    const int sp = bid % (NT * NT * NT);
    const int cog = (bid / (NT * NT * NT)) % (CO / 32);
    const int b = bid / ((NT * NT * NT) * (CO / 32));
    const int tz0 = (sp / (NT * NT)) * 4;
    const int ty0 = ((sp / NT) % NT) * 4;
    const int tx0 = (sp % NT) * 4;
    const int co_base = cog * 32;
    const int tx = tid & 15, ty = tid >> 4;
    const int dz = tx >> 2, dy = tx & 3;

    float acc[4][4];
#pragma unroll
    for (int c = 0; c < 4; c++) {
        float bv = bias[co_base + ty * 4 + c];
#pragma unroll
        for (int s = 0; s < 4; s++) acc[c][s] = bv;
    }
    const float* inb = in + (long long)b * in_bstr;

    for (int ci0 = 0; ci0 < CI; ci0 += 8) {
        __syncthreads();
        // input halo tile 8ci x 6x6x6 (zero padded)
        for (int idx = tid; idx < 8 * 216; idx += 128) {
            int ci = idx / 216, r = idx % 216;
            int z = r / 36, y = (r % 36) / 6, x = r % 6;
            int gz = tz0 + z - 1, gy = ty0 + y - 1, gx = tx0 + x - 1;
            float v = 0.f;
            if ((unsigned)gz < (unsigned)S && (unsigned)gy < (unsigned)S &&
                (unsigned)gx < (unsigned)S)
                v = inb[(long long)(ci0 + ci) * in_cstr + (gz * S + gy) * S + gx];
            in_s[ci * 224 + r] = v;
        }
        // weights 8ci x 27tap x 32co (co contiguous)
        {
            const float* wp = wt + (long long)ci0 * 27 * CO + co_base;
            for (int idx = tid; idx < 8 * 27 * 32; idx += 128) {
                int rt = idx >> 5, c = idx & 31;
                w_s[idx] = wp[(long long)rt * CO + c];
            }
        }
        __syncthreads();

#pragma unroll 1
        for (int ci = 0; ci < 8; ci++) {
            const float* ip = in_s + ci * 224 + dz * 36 + dy * 6;
            const float* wpp = w_s + ci * 27 * 32 + ty * 4;
#pragma unroll
            for (int kz = 0; kz < 3; kz++) {
#pragma unroll
                for (int ky = 0; ky < 3; ky++) {
                    const float* row = ip + kz * 36 + ky * 6;
                    float r[6];
#pragma unroll
                    for (int i = 0; i < 6; i++) r[i] = row[i];
#pragma unroll
                    for (int kx = 0; kx < 3; kx++) {
                        float4 w = *reinterpret_cast<const float4*>(
                            &wpp[(kz * 9 + ky * 3 + kx) * 32]);
#pragma unroll
                        for (int s = 0; s < 4; s++) {
                            acc[0][s] += w.x * r[kx + s];
                            acc[1][s] += w.y * r[kx + s];
                            acc[2][s] += w.z * r[kx + s];
                            acc[3][s] += w.w * r[kx + s];
                        }
                    }
                }
            }
        }
    }

    __syncthreads();
#pragma unroll
    for (int c = 0; c < 4; c++)
#pragma unroll
        for (int s = 0; s < 4; s++)
            pool_s[(ty * 4 + c) * 64 + dz * 16 + dy * 4 + s] = fmaxf(acc[c][s], 0.f);
    __syncthreads();

    constexpr int SO = S / 2;
    for (int i = tid; i < 256; i += 128) {
        int col = i >> 3, pcell = i & 7;
        int pz = pcell >> 2, py = (pcell >> 1) & 1, px = pcell & 1;
        const float* pp = pool_s + col * 64 + pz * 32 + py * 8 + px * 2;
        float m = fmaxf(fmaxf(fmaxf(pp[0], pp[1]), fmaxf(pp[4], pp[5])),
                        fmaxf(fmaxf(pp[16], pp[17]), fmaxf(pp[20], pp[21])));
        int oz = (tz0 >> 1) + pz, oy = (ty0 >> 1) + py, ox = (tx0 >> 1) + px;
        out[(long long)b * out_bstr + (long long)(co_base + col) * out_cstr +
            (oz * SO + oy) * SO + ox] = m;
    }
}

// ---------------- transpose conv (k=2, stride 2) as 8 tap-GEMMs -----------
// out[b][512+co][2i+r] = bt[co] + sum_ci l2[b][ci][i] * Wt[ci][co][r]
__global__ void __launch_bounds__(256) k_convT(const float* __restrict__ bt,
                                               float* __restrict__ out) {
    __shared__ float As[8][64];
    __shared__ float Bs[8][64];
    const int tid = threadIdx.x;
    const int bid = blockIdx.x;
    const int ig = bid & 7;
    const int cog = (bid >> 3) & 7;
    const int tap = (bid >> 6) & 7;
    const int b = bid >> 9;
    const int co_base = cog * 64, i_base = ig * 64;
    const int tx = tid & 15, ty = tid >> 4;

    float acc[4][4];
#pragma unroll
    for (int c = 0; c < 4; c++) {
        float bv = bt[co_base + ty * 4 + c];
#pragma unroll
        for (int s = 0; s < 4; s++) acc[c][s] = bv;
    }
    const float* Ag = g_wtt + ((long long)tap * 1024) * 512 + co_base;
    const float* Bg = g_l2 + (long long)b * 1024 * 512 + i_base;

    for (int k0 = 0; k0 < 1024; k0 += 8) {
        __syncthreads();
        {
            int kk = tid >> 6, c = tid & 63;
            As[kk][c] = Ag[(long long)(k0 + kk) * 512 + c];
            As[kk + 4][c] = Ag[(long long)(k0 + kk + 4) * 512 + c];
            Bs[kk][c] = Bg[(k0 + kk) * 512 + c];
            Bs[kk + 4][c] = Bg[(k0 + kk + 4) * 512 + c];
        }
        __syncthreads();
#pragma unroll
        for (int kk = 0; kk < 8; kk++) {
            float4 a = *reinterpret_cast<const float4*>(&As[kk][ty * 4]);
            float4 bq = *reinterpret_cast<const float4*>(&Bs[kk][tx * 4]);
            float av[4] = {a.x, a.y, a.z, a.w};
            float bv[4] = {bq.x, bq.y, bq.z, bq.w};
#pragma unroll
            for (int c = 0; c < 4; c++)
#pragma unroll
                for (int s = 0; s < 4; s++) acc[c][s] += av[c] * bv[s];
        }
    }

    const int rd = tap >> 2, rh = (tap >> 1) & 1, rw = tap & 1;
#pragma unroll
    for (int c = 0; c < 4; c++) {
        int ch = 512 + co_base + ty * 4 + c;
#pragma unroll
        for (int s = 0; s < 4; s++) {
            int iglob = i_base + tx * 4 + s;
            int id = iglob >> 6, ih = (iglob >> 3) & 7, iw = iglob & 7;
            int o = (2 * id + rd) * 256 + (2 * ih + rh) * 16 + (2 * iw + rw);
            out[(long long)b * 4194304 + (long long)ch * 4096 + o] = acc[c][s];
        }
    }
}

// ---------------- launch ---------------------------------------------------
extern "C" void kernel_launch(void* const* d_in, const int* in_sizes, int n_in,
                              void* d_out, int out_size) {
    const float* pc = (const float*)d_in[0];
    const float* W1 = (const float*)d_in[1];
    const float* b1 = (const float*)d_in[2];
    const float* W2 = (const float*)d_in[3];
    const float* b2 = (const float*)d_in[4];
    const float* Wc1 = (const float*)d_in[5];
    const float* bc1 = (const float*)d_in[6];
    const float* Wc2 = (const float*)d_in[7];
    const float* bc2 = (const float*)d_in[8];
    const float* Wt = (const float*)d_in[9];
    const float* bt = (const float*)d_in[10];
    float* out = (float*)d_out;

    float *grid_p = nullptr, *l2_p = nullptr, *wc1t_p = nullptr, *wc2t_p = nullptr;
    cudaGetSymbolAddress((void**)&grid_p, g_grid);
    cudaGetSymbolAddress((void**)&l2_p, g_l2);
    cudaGetSymbolAddress((void**)&wc1t_p, g_wc1t);
    cudaGetSymbolAddress((void**)&wc2t_p, g_wc2t);

    // 1. zero voxel grid
    k_zero<<<4096, 256>>>(grid_p, BB * 256 * VX / 4);
    // 2. weight layout transforms
    k_w2t<<<128, 256>>>(W2);
    k_wconv_t<<<2048, 256>>>(Wc1, wc1t_p, 256, 512);
    k_wconv_t<<<8192, 256>>>(Wc2, wc2t_p, 512, 1024);
    k_wtt<<<4096, 256>>>(Wt);
    // 3. point MLP + segment max (200000 pts / 64 per block)
    k_mlp<<<3125, 256>>>(pc, W1, b1, b2);
    // 4. conv1 256->512 @32^3 + relu + pool -> l1 (written into d_out[:, :512])
    k_conv<256, 512, 32><<<16384, 128>>>(grid_p, (long long)256 * VX, VX, wc1t_p,
                                         bc1, out, 4194304LL, 4096);
    // 5. conv2 512->1024 @16^3 + relu + pool -> l2 (reads l1 from d_out)
    k_conv<512, 1024, 16><<<4096, 128>>>(out, 4194304LL, 4096, wc2t_p, bc2, l2_p,
                                         524288LL, 512);
    // 6. transpose conv 1024->512 -> d_out[:, 512:]
    k_convT<<<1024, 256>>>(bt, out);
}

// round 3
// speedup vs baseline: 2.9090x; 2.9090x over previous
#include <cuda_runtime.h>
#include <math.h>
#include <stdint.h>

#define NVOX 32
#define VX 32768           // 32^3
#define BB 2
#define NPTS 100000

// ---------------- scratch (device globals; no allocation allowed) ----------
__device__ float g_grid[BB * 256 * VX];        // voxel feature grid (B,256,32^3)
__device__ float g_l2[BB * 1024 * 512];        // conv2 output (B,1024,8^3)
__device__ float g_w2t[128 * 256];             // W2 transposed [k][co]
__device__ float g_wc1t[256 * 27 * 512];       // Wc1 -> [ci][tap][co] (tf32-rounded)
__device__ float g_wc2t[512 * 27 * 1024];      // Wc2 -> [ci][tap][co] (tf32-rounded)
__device__ float g_wtt[8 * 1024 * 512];        // Wt  -> [tap][ci][co]

__device__ __forceinline__ float to_tf32(float x) {
    uint32_t r;
    asm("cvt.rna.tf32.f32 %0, %1;" : "=r"(r) : "f"(x));
    return __uint_as_float(r);
}

__device__ __forceinline__ void mma8(float* d, const uint32_t* a, uint32_t b0,
                                     uint32_t b1) {
    asm volatile(
        "mma.sync.aligned.m16n8k8.row.col.f32.tf32.tf32.f32 "
        "{%0,%1,%2,%3},{%4,%5,%6,%7},{%8,%9},{%0,%1,%2,%3};"
        : "+f"(d[0]), "+f"(d[1]), "+f"(d[2]), "+f"(d[3])
        : "r"(a[0]), "r"(a[1]), "r"(a[2]), "r"(a[3]), "r"(b0), "r"(b1));
}

// ---------------- zero the grid ------------------------------------------
__global__ void k_zero(float* __restrict__ p, int n4) {
    float4 z = make_float4(0.f, 0.f, 0.f, 0.f);
    for (int i = blockIdx.x * blockDim.x + threadIdx.x; i < n4;
         i += gridDim.x * blockDim.x)
        reinterpret_cast<float4*>(p)[i] = z;
}

// ---------------- weight transforms --------------------------------------
__global__ void k_w2t(const float* __restrict__ w2) {
    int i = blockIdx.x * blockDim.x + threadIdx.x;
    if (i < 128 * 256) {
        int k = i >> 8, co = i & 255;
        g_w2t[i] = w2[co * 128 + k];
    }
}

// w[co][ci][27] -> out[(ci*27+tap)*CO + co], rounded to tf32
__global__ void k_wconv_t(const float* __restrict__ w, float* __restrict__ out,
                          int CI, int CO) {
    long long total = (long long)CI * CO * 27;
    for (long long i = blockIdx.x * (long long)blockDim.x + threadIdx.x; i < total;
         i += (long long)gridDim.x * blockDim.x) {
        int co = (int)(i % CO);
        long long r = i / CO;
        int tap = (int)(r % 27);
        int ci = (int)(r / 27);
        out[i] = to_tf32(w[((long long)co * CI + ci) * 27 + tap]);
    }
}

// Wt[ci(1024)][co(512)][8] -> g_wtt[(tap*1024+ci)*512 + co]
__global__ void k_wtt(const float* __restrict__ w) {
    int total = 8 * 1024 * 512;
    for (int i = blockIdx.x * blockDim.x + threadIdx.x; i < total;
         i += gridDim.x * blockDim.x) {
        int co = i & 511;
        int ci = (i >> 9) & 1023;
        int tap = i >> 19;
        g_wtt[i] = w[(((long long)ci << 9) + co) * 8 + tap];
    }
}

// ---------------- point MLP + segment-max scatter -------------------------
__global__ void __launch_bounds__(256) k_mlp(const float* __restrict__ pc,
                                             const float* __restrict__ W1,
                                             const float* __restrict__ b1,
                                             const float* __restrict__ b2) {
    __shared__ float xcs[64][4];
    __shared__ int pb[64];
    __shared__ float Hs[128][64];
    const int tid = threadIdx.x;
    const int g0 = blockIdx.x * 64;

    if (tid < 64) {
        int g = g0 + tid;
        int b = g / NPTS;
        float x = pc[g * 3 + 0], y = pc[g * 3 + 1], z = pc[g * 3 + 2];
        int ix = (int)floorf((x + 1.f) * 16.f);
        int iy = (int)floorf((y + 1.f) * 16.f);
        int iz = (int)floorf((z + 1.f) * 16.f);
        xcs[tid][0] = x - (ix * 0.0625f + 0.03125f - 1.f);
        xcs[tid][1] = y - (iy * 0.0625f + 0.03125f - 1.f);
        xcs[tid][2] = z - (iz * 0.0625f + 0.03125f - 1.f);
        pb[tid] = b * (256 * VX) + ix * 1024 + iy * 32 + iz;
    }
    __syncthreads();

#pragma unroll
    for (int i = 0; i < 32; i++) {
        int lin = i * 256 + tid;
        int k = lin >> 6, p = lin & 63;
        float a = b1[k] + W1[k * 3 + 0] * xcs[p][0] + W1[k * 3 + 1] * xcs[p][1] +
                  W1[k * 3 + 2] * xcs[p][2];
        Hs[k][p] = fmaxf(a, 0.f);
    }
    __syncthreads();

    const int cg = tid & 31, pg = tid >> 5;
    const int co0 = cg * 8, p0 = pg * 8;
    float acc[8][8];
    {
        float4 bA = *reinterpret_cast<const float4*>(&b2[co0]);
        float4 bB = *reinterpret_cast<const float4*>(&b2[co0 + 4]);
        float bi[8] = {bA.x, bA.y, bA.z, bA.w, bB.x, bB.y, bB.z, bB.w};
#pragma unroll
        for (int c = 0; c < 8; c++)
#pragma unroll
            for (int p = 0; p < 8; p++) acc[c][p] = bi[c];
    }
#pragma unroll 4
    for (int k = 0; k < 128; k++) {
        float4 wA = *reinterpret_cast<const float4*>(&g_w2t[k * 256 + co0]);
        float4 wB = *reinterpret_cast<const float4*>(&g_w2t[k * 256 + co0 + 4]);
        float4 hA = *reinterpret_cast<const float4*>(&Hs[k][p0]);
        float4 hB = *reinterpret_cast<const float4*>(&Hs[k][p0 + 4]);
        float wv[8] = {wA.x, wA.y, wA.z, wA.w, wB.x, wB.y, wB.z, wB.w};
        float hv[8] = {hA.x, hA.y, hA.z, hA.w, hB.x, hB.y, hB.z, hB.w};
#pragma unroll
        for (int c = 0; c < 8; c++)
#pragma unroll
            for (int p = 0; p < 8; p++) acc[c][p] += wv[c] * hv[p];
    }
#pragma unroll
    for (int c = 0; c < 8; c++) {
        int cob = (co0 + c) * VX;
#pragma unroll
        for (int p = 0; p < 8; p++) {
            float v = acc[c][p];
            if (v > 0.f)
                atomicMax(reinterpret_cast<int*>(&g_grid[pb[p0 + p] + cob]),
                          __float_as_int(v));
        }
    }
}

// ---------------- tf32 MMA conv3d (k=3, pad=1) + relu + maxpool2 ----------
// Block: 128 c_out x (4z,4y,8x)=128 spatial. 256 threads = 8 warps:
// 4 co-warps (M=32) x 2 n-warps (N=64). c_in chunk=8 = one k8 MMA step/tap.
// Smem: halo[8ci][6][6][10] stride 360; W[tap*8+k][136] (conflict-free frags).
template <int CI, int CO, int S>
__global__ void __launch_bounds__(256, 1) k_cmma(const float* __restrict__ in,
                                                 long long in_bstr, int in_cstr,
                                                 const float* __restrict__ wt,
                                                 const float* __restrict__ bias,
                                                 float* __restrict__ out,
                                                 long long out_bstr, int out_cstr) {
    constexpr int NTX = S / 8, NTY = S / 4, NTZ = S / 4;
    constexpr int NSP = NTX * NTY * NTZ;
    constexpr int HALO = 8 * 360;          // 2880 floats
    constexpr int WROW = 136;

    extern __shared__ float sm[];
    float* halo = sm;
    float* ws = sm + HALO;
    float* ps = ws;                        // pool overlay (needs 128*132 <= 29376)

    const int tid = threadIdx.x;
    const int lane = tid & 31;
    const int wid = tid >> 5;
    const int cw = (wid & 3) * 32;         // warp co offset in tile
    const int nw = (wid >> 2) * 64;        // warp spatial offset in tile

    const int bid = blockIdx.x;
    const int sp = bid % NSP;
    const int cog = (bid / NSP) % (CO / 128);
    const int b = bid / (NSP * (CO / 128));
    const int tz0 = (sp / (NTY * NTX)) * 4;
    const int ty0 = ((sp / NTX) % NTY) * 4;
    const int tx0 = (sp % NTX) * 8;
    const int cobase = cog * 128;

    // per-thread spatial offsets of its 8 B-columns within the halo tile
    int offj[8];
#pragma unroll
    for (int j = 0; j < 8; j++) {
        int n = nw + j * 8 + (lane >> 2);
        int z = n >> 5, y = (n >> 3) & 3, x = n & 7;
        offj[j] = z * 60 + y * 10 + x;
    }

    float d[2][8][4];
#pragma unroll
    for (int mt = 0; mt < 2; mt++) {
        int co = cobase + cw + mt * 16 + (lane >> 2);
        float blo = bias[co], bhi = bias[co + 8];
#pragma unroll
        for (int j = 0; j < 8; j++) {
            d[mt][j][0] = blo; d[mt][j][1] = blo;
            d[mt][j][2] = bhi; d[mt][j][3] = bhi;
        }
    }

    const float* inb = in + (long long)b * in_bstr;

    for (int ci0 = 0; ci0 < CI; ci0 += 8) {
        __syncthreads();
        // stage halo (zero padded, tf32 rounded)
        for (int idx = tid; idx < HALO; idx += 256) {
            int ci = idx / 360, r = idx % 360;
            int z = r / 60, y = (r % 60) / 10, x = r % 10;
            int gz = tz0 + z - 1, gy = ty0 + y - 1, gx = tx0 + x - 1;
            float v = 0.f;
            if ((unsigned)gz < (unsigned)S && (unsigned)gy < (unsigned)S &&
                (unsigned)gx < (unsigned)S)
                v = inb[(long long)(ci0 + ci) * in_cstr + (gz * S + gy) * S + gx];
            halo[idx] = to_tf32(v);
        }
        // stage weights: ws[(tap*8+k)*136 + co], gmem already tf32-rounded
        for (int idx = tid; idx < 27 * 8 * 32; idx += 256) {
            int r = idx >> 5, c4 = idx & 31;
            int k = r & 7, tap = r >> 3;
            float4 v = *reinterpret_cast<const float4*>(
                wt + (((long long)(ci0 + k) * 27 + tap) * CO + cobase + c4 * 4));
            float* w = ws + (tap * 8 + k) * WROW + c4 * 4;
            w[0] = v.x; w[1] = v.y; w[2] = v.z; w[3] = v.w;
        }
        __syncthreads();

#pragma unroll
        for (int kz = 0; kz < 3; kz++) {
#pragma unroll
            for (int ky = 0; ky < 3; ky++) {
#pragma unroll
                for (int kx = 0; kx < 3; kx++) {
                    const int tap = kz * 9 + ky * 3 + kx;
                    const int toff = kz * 60 + ky * 10 + kx;
                    // A fragments (2 m-tiles)
                    uint32_t a[2][4];
                    const float* aw =
                        ws + (tap * 8 + (lane & 3)) * WROW + cw + (lane >> 2);
#pragma unroll
                    for (int mt = 0; mt < 2; mt++) {
                        const float* p = aw + mt * 16;
                        a[mt][0] = __float_as_uint(p[0]);
                        a[mt][1] = __float_as_uint(p[8]);
                        a[mt][2] = __float_as_uint(p[4 * WROW]);
                        a[mt][3] = __float_as_uint(p[4 * WROW + 8]);
                    }
                    const float* hb = halo + (lane & 3) * 360 + toff;
#pragma unroll
                    for (int j = 0; j < 8; j++) {
                        uint32_t b0 = __float_as_uint(hb[offj[j]]);
                        uint32_t b1 = __float_as_uint(hb[offj[j] + 4 * 360]);
                        mma8(d[0][j], a[0], b0, b1);
                        mma8(d[1][j], a[1], b0, b1);
                    }
                }
            }
        }
    }

    // epilogue: relu -> pool smem (stride 132) -> 2x2x2 maxpool -> gmem
    __syncthreads();
#pragma unroll
    for (int mt = 0; mt < 2; mt++) {
        int co_l = cw + mt * 16 + (lane >> 2);
#pragma unroll
        for (int j = 0; j < 8; j++) {
            int nb = nw + j * 8 + (lane & 3) * 2;
            ps[co_l * 132 + nb] = fmaxf(d[mt][j][0], 0.f);
            ps[co_l * 132 + nb + 1] = fmaxf(d[mt][j][1], 0.f);
            ps[(co_l + 8) * 132 + nb] = fmaxf(d[mt][j][2], 0.f);
            ps[(co_l + 8) * 132 + nb + 1] = fmaxf(d[mt][j][3], 0.f);
        }
    }
    __syncthreads();

    constexpr int SO = S / 2;
    for (int o = tid; o < 128 * 16; o += 256) {
        int co_l = o >> 4, cell = o & 15;
        int pz = cell >> 3, py = (cell >> 2) & 1, px = cell & 3;
        const float* pp = ps + co_l * 132 + pz * 64 + py * 16 + px * 2;
        float m = fmaxf(fmaxf(fmaxf(pp[0], pp[1]), fmaxf(pp[8], pp[9])),
                        fmaxf(fmaxf(pp[32], pp[33]), fmaxf(pp[40], pp[41])));
        int oz = (tz0 >> 1) + pz, oy = (ty0 >> 1) + py, ox = (tx0 >> 1) + px;
        out[(long long)b * out_bstr + (long long)(cobase + co_l) * out_cstr +
            (oz * SO + oy) * SO + ox] = m;
    }
}

// ---------------- transpose conv (k=2, stride 2) as 8 tap-GEMMs -----------
__global__ void __launch_bounds__(256) k_convT(const float* __restrict__ bt,
                                               float* __restrict__ out) {
    __shared__ float As[8][64];
    __shared__ float Bs[8][64];
    const int tid = threadIdx.x;
    const int bid = blockIdx.x;
    const int ig = bid & 7;
    const int cog = (bid >> 3) & 7;
    const int tap = (bid >> 6) & 7;
    const int b = bid >> 9;
    const int co_base = cog * 64, i_base = ig * 64;
    const int tx = tid & 15, ty = tid >> 4;

    float acc[4][4];
#pragma unroll
    for (int c = 0; c < 4; c++) {
        float bv = bt[co_base + ty * 4 + c];
#pragma unroll
        for (int s = 0; s < 4; s++) acc[c][s] = bv;
    }
    const float* Ag = g_wtt + ((long long)tap * 1024) * 512 + co_base;
    const float* Bg = g_l2 + (long long)b * 1024 * 512 + i_base;

    for (int k0 = 0; k0 < 1024; k0 += 8) {
        __syncthreads();
        {
            int kk = tid >> 6, c = tid & 63;
            As[kk][c] = Ag[(long long)(k0 + kk) * 512 + c];
            As[kk + 4][c] = Ag[(long long)(k0 + kk + 4) * 512 + c];
            Bs[kk][c] = Bg[(k0 + kk) * 512 + c];
            Bs[kk + 4][c] = Bg[(k0 + kk + 4) * 512 + c];
        }
        __syncthreads();
#pragma unroll
        for (int kk = 0; kk < 8; kk++) {
            float4 a = *reinterpret_cast<const float4*>(&As[kk][ty * 4]);
            float4 bq = *reinterpret_cast<const float4*>(&Bs[kk][tx * 4]);
            float av[4] = {a.x, a.y, a.z, a.w};
            float bv[4] = {bq.x, bq.y, bq.z, bq.w};
#pragma unroll
            for (int c = 0; c < 4; c++)
#pragma unroll
                for (int s = 0; s < 4; s++) acc[c][s] += av[c] * bv[s];
        }
    }

    const int rd = tap >> 2, rh = (tap >> 1) & 1, rw = tap & 1;
#pragma unroll
    for (int c = 0; c < 4; c++) {
        int ch = 512 + co_base + ty * 4 + c;
#pragma unroll
        for (int s = 0; s < 4; s++) {
            int iglob = i_base + tx * 4 + s;
            int id = iglob >> 6, ih = (iglob >> 3) & 7, iw = iglob & 7;
            int o = (2 * id + rd) * 256 + (2 * ih + rh) * 16 + (2 * iw + rw);
            out[(long long)b * 4194304 + (long long)ch * 4096 + o] = acc[c][s];
        }
    }
}

// ---------------- launch ---------------------------------------------------
extern "C" void kernel_launch(void* const* d_in, const int* in_sizes, int n_in,
                              void* d_out, int out_size) {
    const float* pc = (const float*)d_in[0];
    const float* W1 = (const float*)d_in[1];
    const float* b1 = (const float*)d_in[2];
    const float* W2 = (const float*)d_in[3];
    const float* b2 = (const float*)d_in[4];
    const float* Wc1 = (const float*)d_in[5];
    const float* bc1 = (const float*)d_in[6];
    const float* Wc2 = (const float*)d_in[7];
    const float* bc2 = (const float*)d_in[8];
    const float* Wt = (const float*)d_in[9];
    const float* bt = (const float*)d_in[10];
    float* out = (float*)d_out;

    float *grid_p = nullptr, *l2_p = nullptr, *wc1t_p = nullptr, *wc2t_p = nullptr;
    cudaGetSymbolAddress((void**)&grid_p, g_grid);
    cudaGetSymbolAddress((void**)&l2_p, g_l2);
    cudaGetSymbolAddress((void**)&wc1t_p, g_wc1t);
    cudaGetSymbolAddress((void**)&wc2t_p, g_wc2t);

    const int smem_bytes = (2880 + 27 * 8 * 136) * 4;   // 129024
    cudaFuncSetAttribute(k_cmma<256, 512, 32>,
                         cudaFuncAttributeMaxDynamicSharedMemorySize, smem_bytes);
    cudaFuncSetAttribute(k_cmma<512, 1024, 16>,
                         cudaFuncAttributeMaxDynamicSharedMemorySize, smem_bytes);

    // 1. zero voxel grid
    k_zero<<<4096, 256>>>(grid_p, BB * 256 * VX / 4);
    // 2. weight layout transforms (conv weights tf32-rounded here)
    k_w2t<<<128, 256>>>(W2);
    k_wconv_t<<<2048, 256>>>(Wc1, wc1t_p, 256, 512);
    k_wconv_t<<<8192, 256>>>(Wc2, wc2t_p, 512, 1024);
    k_wtt<<<4096, 256>>>(Wt);
    // 3. point MLP + segment max
    k_mlp<<<3125, 256>>>(pc, W1, b1, b2);
    // 4. conv1 256->512 @32^3 + relu + pool -> d_out[:, :512]
    k_cmma<256, 512, 32><<<256 * 4 * 2, 256, smem_bytes>>>(
        grid_p, (long long)256 * VX, VX, wc1t_p, bc1, out, 4194304LL, 4096);
    // 5. conv2 512->1024 @16^3 + relu + pool -> g_l2
    k_cmma<512, 1024, 16><<<32 * 8 * 2, 256, smem_bytes>>>(
        out, 4194304LL, 4096, wc2t_p, bc2, l2_p, 524288LL, 512);
    // 6. transpose conv 1024->512 -> d_out[:, 512:]
    k_convT<<<1024, 256>>>(bt, out);
}